// round 3
// baseline (speedup 1.0000x reference)
#include <cuda_runtime.h>
#include <cuda_bf16.h>
#include <math.h>
#include <stdint.h>

#define SS 8192
#define TT 48
#define STARTT 46
#define ENDT 47

// ---------------- scratch (device globals; no allocation allowed) ----------------
__device__ __align__(16) float g_pre[2][SS * 1024];   // x @ W_ih^T + biases, per direction
__device__ __align__(16) float g_hf[SS * 256];        // forward hidden states
__device__ __align__(16) float g_hb[SS * 256];        // backward hidden states (natural order)
__device__ __align__(16) float g_l[SS * 256];         // char-CNN features
__device__ __align__(16) float g_feats[SS * TT];      // emissions
__device__ float g_gold;

// =======================================================================
// Kernel 1: fused input-projection GEMM (both dirs) + char CNN
// grid: 4096 GEMM blocks + 2048 CNN blocks, 256 threads
// =======================================================================
template <int K>
__device__ __forceinline__ float conv_max(const float (*ce)[16], const float* __restrict__ w, float b) {
    float wr[17 * K];
#pragma unroll
    for (int i = 0; i < 17 * K; i++) wr[i] = __ldg(&w[i]);
    float m = -1e30f;
#pragma unroll
    for (int p = 0; p < 16 - K + 1; p++) {
        float acc = b;
#pragma unroll
        for (int c = 0; c < 17; c++)
#pragma unroll
            for (int k = 0; k < K; k++) acc = fmaf(ce[c][p + k], wr[c * K + k], acc);
        m = fmaxf(m, acc);
    }
    return m;
}

__global__ __launch_bounds__(256) void k_gemm_cnn(
    const float* __restrict__ x,
    const float* __restrict__ Wf, const float* __restrict__ Wb,
    const float* __restrict__ bihf, const float* __restrict__ bhhf,
    const float* __restrict__ bihb, const float* __restrict__ bhhb,
    const int* __restrict__ char_list, const float* __restrict__ emb,
    const float* __restrict__ cw1, const float* __restrict__ cb1,
    const float* __restrict__ cw2, const float* __restrict__ cb2,
    const float* __restrict__ cw3, const float* __restrict__ cb3,
    const float* __restrict__ cw4, const float* __restrict__ cb4)
{
    const int tid = threadIdx.x;
    const int bid = blockIdx.x;

    if (bid < 4096) {
        // ---- GEMM: pre[dir][m][n] = sum_k x[m][k]*W[n][k] + b_ih[n]+b_hh[n] ----
        __shared__ float As[16 * 68];
        __shared__ float Bs[16 * 68];
        const int bm = bid >> 5, bn = bid & 31;
        const int m0 = bm * 64, n0 = bn * 64;
        const int dir = n0 >> 10;
        const int ncol0 = n0 & 1023;
        const float* W = dir ? Wb : Wf;
        const int tx = tid & 15, ty = tid >> 4;
        const int aRow = tid >> 2, aK = (tid & 3) << 2;
        float acc[4][4];
#pragma unroll
        for (int i = 0; i < 4; i++)
#pragma unroll
            for (int j = 0; j < 4; j++) acc[i][j] = 0.f;

        for (int k0 = 0; k0 < 256; k0 += 16) {
            float4 a4 = *reinterpret_cast<const float4*>(&x[(m0 + aRow) * 256 + k0 + aK]);
            float4 b4 = *reinterpret_cast<const float4*>(&W[(ncol0 + aRow) * 256 + k0 + aK]);
            As[(aK + 0) * 68 + aRow] = a4.x; As[(aK + 1) * 68 + aRow] = a4.y;
            As[(aK + 2) * 68 + aRow] = a4.z; As[(aK + 3) * 68 + aRow] = a4.w;
            Bs[(aK + 0) * 68 + aRow] = b4.x; Bs[(aK + 1) * 68 + aRow] = b4.y;
            Bs[(aK + 2) * 68 + aRow] = b4.z; Bs[(aK + 3) * 68 + aRow] = b4.w;
            __syncthreads();
#pragma unroll
            for (int kk = 0; kk < 16; kk++) {
                float ar[4], br[4];
#pragma unroll
                for (int i = 0; i < 4; i++) ar[i] = As[kk * 68 + ty * 4 + i];
#pragma unroll
                for (int j = 0; j < 4; j++) br[j] = Bs[kk * 68 + tx * 4 + j];
#pragma unroll
                for (int i = 0; i < 4; i++)
#pragma unroll
                    for (int j = 0; j < 4; j++) acc[i][j] = fmaf(ar[i], br[j], acc[i][j]);
            }
            __syncthreads();
        }
        const float* bI = dir ? bihb : bihf;
        const float* bH = dir ? bhhb : bhhf;
#pragma unroll
        for (int j = 0; j < 4; j++) {
            int col = ncol0 + tx * 4 + j;
            float bias = bI[col] + bH[col];
#pragma unroll
            for (int i = 0; i < 4; i++)
                g_pre[dir][(m0 + ty * 4 + i) * 1024 + col] = acc[i][j] + bias;
        }
    } else {
        // ---- char CNN: 4 tokens per block, 64 threads per token ----
        __shared__ float ce_s[4][17][16];
        __shared__ int cl_s[4][16];
        const int s0 = (bid - 4096) * 4;
        if (tid < 64) {
            int tk = tid >> 4, w = tid & 15;
            cl_s[tk][w] = char_list[(s0 + tk) * 16 + w];
        }
        __syncthreads();
        for (int idx = tid; idx < 1088; idx += 256) {
            int tk = idx / 272, r = idx % 272;
            int c = r >> 4, w = r & 15;
            ce_s[tk][c][w] = __ldg(&emb[cl_s[tk][w] * 17 + c]);
        }
        __syncthreads();
        const int tl = tid >> 6, o = tid & 63;
        const int s = s0 + tl;
        float r1 = conv_max<2>(ce_s[tl], cw1 + o * 34, cb1[o]);
        float r2 = conv_max<2>(ce_s[tl], cw2 + o * 34, cb2[o]);
        float r3 = conv_max<3>(ce_s[tl], cw3 + o * 51, cb3[o]);
        float r4 = conv_max<3>(ce_s[tl], cw4 + o * 51, cb4[o]);
        g_l[s * 256 + 0 + o] = r1;
        g_l[s * 256 + 64 + o] = r2;
        g_l[s * 256 + 128 + o] = r3;
        g_l[s * 256 + 192 + o] = r4;
    }
}

// =======================================================================
// Kernel 2: BiLSTM recurrence. grid=16, two 8-CTA clusters (fwd/bwd).
// W_hh register-resident; h exchanged via DSMEM + cluster barrier.
// =======================================================================
__global__ void __cluster_dims__(8, 1, 1) __launch_bounds__(256, 1)
k_lstm(const float* __restrict__ Whh_f, const float* __restrict__ Whh_b)
{
    __shared__ __align__(16) float hbuf[2][264]; // h[0..127]@[0..127], h[128..255]@[132..259]
    __shared__ float gates_s[128];

    const int tid = threadIdx.x;
    const int rank = blockIdx.x & 7;
    const int dir = blockIdx.x >> 3;
    const float* __restrict__ Whh = dir ? Whh_b : Whh_f;
    const float* __restrict__ pre = g_pre[dir];
    float* __restrict__ hout = dir ? g_hb : g_hf;

    const int lane = tid & 31;
    const int wrp = tid >> 5;                      // 0..7
    const int row_local = wrp * 16 + (lane & 15);  // 0..127 = gate*32 + hu_local
    const int half = lane >> 4;                    // which 128-half of h this thread dots
    const int hoff = half * 132;
    const int gate = row_local >> 5;
    const int hu_local = row_local & 31;
    const int grow = gate * 256 + rank * 32 + hu_local;  // row of W_hh (and of pre)

    // load my 128 W_hh weights into registers
    float4 w4[32];
    const float4* wp = reinterpret_cast<const float4*>(Whh + grow * 256 + half * 128);
#pragma unroll
    for (int q = 0; q < 32; q++) w4[q] = __ldg(&wp[q]);

    for (int i = tid; i < 264; i += 256) { hbuf[0][i] = 0.f; hbuf[1][i] = 0.f; }
    float c = 0.f;
    __syncthreads();
    asm volatile("barrier.cluster.arrive.aligned;" ::: "memory");
    asm volatile("barrier.cluster.wait.aligned;" ::: "memory");

    float preval = (half == 0) ? __ldg(&pre[(dir ? (SS - 1) : 0) * 1024 + grow]) : 0.f;

    int p = 0;
    for (int t = 0; t < SS; t++) {
        const int tin = dir ? (SS - 1 - t) : t;

        // matvec: my half of h dot my weight row
        const float4* h4 = reinterpret_cast<const float4*>(&hbuf[p][hoff]);
        float a0 = 0.f, a1 = 0.f, a2 = 0.f, a3 = 0.f;
#pragma unroll
        for (int q = 0; q < 32; q += 4) {
            float4 h0 = h4[q], hA = h4[q + 1], hB = h4[q + 2], hC = h4[q + 3];
            float4 v0 = w4[q], vA = w4[q + 1], vB = w4[q + 2], vC = w4[q + 3];
            a0 = fmaf(v0.x, h0.x, fmaf(v0.y, h0.y, fmaf(v0.z, h0.z, fmaf(v0.w, h0.w, a0))));
            a1 = fmaf(vA.x, hA.x, fmaf(vA.y, hA.y, fmaf(vA.z, hA.z, fmaf(vA.w, hA.w, a1))));
            a2 = fmaf(vB.x, hB.x, fmaf(vB.y, hB.y, fmaf(vB.z, hB.z, fmaf(vB.w, hB.w, a2))));
            a3 = fmaf(vC.x, hC.x, fmaf(vC.y, hC.y, fmaf(vC.z, hC.z, fmaf(vC.w, hC.w, a3))));
        }
        float acc = (a0 + a1) + (a2 + a3);
        acc += __shfl_xor_sync(0xffffffffu, acc, 16);  // combine the two halves
        if (half == 0) gates_s[row_local] = acc + preval;
        __syncthreads();

        // gate combine + h update: this CTA owns hidden units rank*32..rank*32+31
        if (tid < 32) {
            float gi = gates_s[tid];
            float gf = gates_s[32 + tid];
            float gg = gates_s[64 + tid];
            float go = gates_s[96 + tid];
            float si = 1.f / (1.f + __expf(-gi));
            float sf = 1.f / (1.f + __expf(-gf));
            float so = 1.f / (1.f + __expf(-go));
            c = sf * c + si * tanhf(gg);
            float hval = so * tanhf(c);
            int hu = rank * 32 + tid;
            int hidx = (hu < 128) ? hu : (hu + 4);
            uint32_t addr = (uint32_t)__cvta_generic_to_shared(&hbuf[1 - p][hidx]);
#pragma unroll
            for (int pr = 0; pr < 8; pr++) {
                uint32_t pa;
                asm volatile("mapa.shared::cluster.u32 %0, %1, %2;" : "=r"(pa) : "r"(addr), "r"(pr));
                asm volatile("st.shared::cluster.f32 [%0], %1;" :: "r"(pa), "f"(hval) : "memory");
            }
            hout[tin * 256 + hu] = hval;
        }
        asm volatile("barrier.cluster.arrive.aligned;" ::: "memory");
        // prefetch next step's pre while the barrier drains
        int tnext = dir ? max(SS - 2 - t, 0) : min(t + 1, SS - 1);
        float pnext = (half == 0) ? __ldg(&pre[tnext * 1024 + grow]) : 0.f;
        asm volatile("barrier.cluster.wait.aligned;" ::: "memory");
        preval = pnext;
        p ^= 1;
    }
}

// =======================================================================
// Kernel 3: dense emissions  feats = [hf|hb|x|l] @ dense_W^T + b
// grid: 1024 x 384 (8 tokens/block, 48 tags)
// =======================================================================
__global__ __launch_bounds__(384) void k_dense(
    const float* __restrict__ x, const float* __restrict__ dW, const float* __restrict__ db)
{
    const int t = blockIdx.x * 8 + threadIdx.x / 48;
    const int j = threadIdx.x % 48;
    const float* __restrict__ w = dW + j * 1024;
    const float* segs[4] = { g_hf + t * 256, g_hb + t * 256, x + t * 256, g_l + t * 256 };
    float acc[4] = { db[j], 0.f, 0.f, 0.f };
#pragma unroll
    for (int sgi = 0; sgi < 4; sgi++) {
        const float4* sv = reinterpret_cast<const float4*>(segs[sgi]);
        const float4* wv = reinterpret_cast<const float4*>(w + sgi * 256);
#pragma unroll 8
        for (int q = 0; q < 64; q++) {
            float4 a = sv[q];
            float4 b = __ldg(&wv[q]);
            acc[q & 3] = fmaf(a.x, b.x, fmaf(a.y, b.y, fmaf(a.z, b.z, fmaf(a.w, b.w, acc[q & 3]))));
        }
    }
    g_feats[t * 48 + j] = (acc[0] + acc[1]) + (acc[2] + acc[3]);
}

// =======================================================================
// Kernel 4: gold path score
// =======================================================================
__global__ __launch_bounds__(256) void k_gold(const int* __restrict__ tags, const float* __restrict__ trans)
{
    __shared__ float red[256];
    const int tid = threadIdx.x;
    float s = 0.f;
    for (int t = tid; t < SS; t += 256) {
        int tg = tags[t];
        s += g_feats[t * 48 + tg];
        int prev = (t == 0) ? STARTT : tags[t - 1];
        s += trans[tg * 48 + prev];
    }
    if (tid == 0) s += trans[ENDT * 48 + tags[SS - 1]];
    red[tid] = s;
    __syncthreads();
    for (int off = 128; off; off >>= 1) {
        if (tid < off) red[tid] += red[tid + off];
        __syncthreads();
    }
    if (tid == 0) g_gold = red[0];
}

// =======================================================================
// Kernel 5: CRF forward scan + final NLL.  384 threads = 48 tags x 8 lanes
// =======================================================================
__global__ __launch_bounds__(384) void k_crf(const float* __restrict__ trans, float* __restrict__ out)
{
    __shared__ float alpha[2][48];
    __shared__ float fin[48];
    const int tid = threadIdx.x;
    const int j = tid >> 3, g = tid & 7, i0 = g * 6;
    float trs[6];
#pragma unroll
    for (int u = 0; u < 6; u++) trs[u] = trans[j * 48 + i0 + u];
    if (tid < 48) alpha[0][tid] = (tid == STARTT) ? 0.f : -10000.f;
    __syncthreads();

    float fcur = __ldg(&g_feats[j]);
    int p = 0;
    for (int t = 0; t < SS; t++) {
        float fnext = __ldg(&g_feats[min(t + 1, SS - 1) * 48 + j]);
        float v[6];
#pragma unroll
        for (int u = 0; u < 6; u++) v[u] = alpha[p][i0 + u] + trs[u];
        float m = v[0];
#pragma unroll
        for (int u = 1; u < 6; u++) m = fmaxf(m, v[u]);
        m = fmaxf(m, __shfl_xor_sync(0xffffffffu, m, 1, 8));
        m = fmaxf(m, __shfl_xor_sync(0xffffffffu, m, 2, 8));
        m = fmaxf(m, __shfl_xor_sync(0xffffffffu, m, 4, 8));
        float sexp = 0.f;
#pragma unroll
        for (int u = 0; u < 6; u++) sexp += __expf(v[u] - m);
        sexp += __shfl_xor_sync(0xffffffffu, sexp, 1, 8);
        sexp += __shfl_xor_sync(0xffffffffu, sexp, 2, 8);
        sexp += __shfl_xor_sync(0xffffffffu, sexp, 4, 8);
        float res = m + __logf(sexp) + fcur;
        if (g == 0) alpha[1 - p][j] = res;
        __syncthreads();
        fcur = fnext;
        p ^= 1;
    }
    if (tid < 48) fin[tid] = alpha[p][tid] + trans[ENDT * 48 + tid];
    __syncthreads();
    if (tid == 0) {
        float m = fin[0];
        for (int i = 1; i < 48; i++) m = fmaxf(m, fin[i]);
        float ss = 0.f;
        for (int i = 0; i < 48; i++) ss += expf(fin[i] - m);
        out[0] = m + logf(ss) - g_gold;
    }
}

// =======================================================================
extern "C" void kernel_launch(void* const* d_in, const int* in_sizes, int n_in,
                              void* d_out, int out_size)
{
    const float* sentence  = (const float*)d_in[0];
    const int*   char_list = (const int*)d_in[1];
    const int*   tags      = (const int*)d_in[2];
    const float* emb       = (const float*)d_in[3];
    const float* trans     = (const float*)d_in[4];
    const float* W_ih_f    = (const float*)d_in[5];
    const float* W_hh_f    = (const float*)d_in[6];
    const float* b_ih_f    = (const float*)d_in[7];
    const float* b_hh_f    = (const float*)d_in[8];
    const float* W_ih_b    = (const float*)d_in[9];
    const float* W_hh_b    = (const float*)d_in[10];
    const float* b_ih_b    = (const float*)d_in[11];
    const float* b_hh_b    = (const float*)d_in[12];
    const float* dense_W   = (const float*)d_in[13];
    const float* dense_b   = (const float*)d_in[14];
    const float* cw1 = (const float*)d_in[15];
    const float* cb1 = (const float*)d_in[16];
    const float* cw2 = (const float*)d_in[17];
    const float* cb2 = (const float*)d_in[18];
    const float* cw3 = (const float*)d_in[19];
    const float* cb3 = (const float*)d_in[20];
    const float* cw4 = (const float*)d_in[21];
    const float* cb4 = (const float*)d_in[22];
    float* out = (float*)d_out;

    k_gemm_cnn<<<6144, 256>>>(sentence, W_ih_f, W_ih_b,
                              b_ih_f, b_hh_f, b_ih_b, b_hh_b,
                              char_list, emb,
                              cw1, cb1, cw2, cb2, cw3, cb3, cw4, cb4);
    k_lstm<<<16, 256>>>(W_hh_f, W_hh_b);
    k_dense<<<1024, 384>>>(sentence, dense_W, dense_b);
    k_gold<<<1, 256>>>(tags, trans);
    k_crf<<<1, 384>>>(trans, out);
}

// round 6
// speedup vs baseline: 1.6435x; 1.6435x over previous
#include <cuda_runtime.h>
#include <cuda_bf16.h>
#include <math.h>
#include <stdint.h>

#define SS 8192
#define TT 48
#define STARTT 46
#define ENDT 47

// ---------------- scratch (device globals; no allocation allowed) ----------------
__device__ __align__(16) float g_pre[2][SS * 1024];   // x @ W_ih^T + biases, per direction
__device__ __align__(16) float g_hf[SS * 256];        // forward hidden states
__device__ __align__(16) float g_hb[SS * 256];        // backward hidden states (natural order)
__device__ __align__(16) float g_l[SS * 256];         // char-CNN features
__device__ __align__(16) float g_feats[SS * TT];      // emissions
__device__ float g_gold;

// =======================================================================
// Kernel 1: fused input-projection GEMM (both dirs) + char CNN
// =======================================================================
template <int K>
__device__ __forceinline__ float conv_max(const float (*ce)[16], const float* __restrict__ w, float b) {
    float wr[17 * K];
#pragma unroll
    for (int i = 0; i < 17 * K; i++) wr[i] = __ldg(&w[i]);
    float m = -1e30f;
#pragma unroll
    for (int p = 0; p < 16 - K + 1; p++) {
        float acc = b;
#pragma unroll
        for (int c = 0; c < 17; c++)
#pragma unroll
            for (int k = 0; k < K; k++) acc = fmaf(ce[c][p + k], wr[c * K + k], acc);
        m = fmaxf(m, acc);
    }
    return m;
}

__global__ __launch_bounds__(256) void k_gemm_cnn(
    const float* __restrict__ x,
    const float* __restrict__ Wf, const float* __restrict__ Wb,
    const float* __restrict__ bihf, const float* __restrict__ bhhf,
    const float* __restrict__ bihb, const float* __restrict__ bhhb,
    const int* __restrict__ char_list, const float* __restrict__ emb,
    const float* __restrict__ cw1, const float* __restrict__ cb1,
    const float* __restrict__ cw2, const float* __restrict__ cb2,
    const float* __restrict__ cw3, const float* __restrict__ cb3,
    const float* __restrict__ cw4, const float* __restrict__ cb4)
{
    const int tid = threadIdx.x;
    const int bid = blockIdx.x;

    if (bid < 4096) {
        __shared__ float As[16 * 68];
        __shared__ float Bs[16 * 68];
        const int bm = bid >> 5, bn = bid & 31;
        const int m0 = bm * 64, n0 = bn * 64;
        const int dir = n0 >> 10;
        const int ncol0 = n0 & 1023;
        const float* W = dir ? Wb : Wf;
        const int tx = tid & 15, ty = tid >> 4;
        const int aRow = tid >> 2, aK = (tid & 3) << 2;
        float acc[4][4];
#pragma unroll
        for (int i = 0; i < 4; i++)
#pragma unroll
            for (int j = 0; j < 4; j++) acc[i][j] = 0.f;

        for (int k0 = 0; k0 < 256; k0 += 16) {
            float4 a4 = *reinterpret_cast<const float4*>(&x[(m0 + aRow) * 256 + k0 + aK]);
            float4 b4 = *reinterpret_cast<const float4*>(&W[(ncol0 + aRow) * 256 + k0 + aK]);
            As[(aK + 0) * 68 + aRow] = a4.x; As[(aK + 1) * 68 + aRow] = a4.y;
            As[(aK + 2) * 68 + aRow] = a4.z; As[(aK + 3) * 68 + aRow] = a4.w;
            Bs[(aK + 0) * 68 + aRow] = b4.x; Bs[(aK + 1) * 68 + aRow] = b4.y;
            Bs[(aK + 2) * 68 + aRow] = b4.z; Bs[(aK + 3) * 68 + aRow] = b4.w;
            __syncthreads();
#pragma unroll
            for (int kk = 0; kk < 16; kk++) {
                float ar[4], br[4];
#pragma unroll
                for (int i = 0; i < 4; i++) ar[i] = As[kk * 68 + ty * 4 + i];
#pragma unroll
                for (int j = 0; j < 4; j++) br[j] = Bs[kk * 68 + tx * 4 + j];
#pragma unroll
                for (int i = 0; i < 4; i++)
#pragma unroll
                    for (int j = 0; j < 4; j++) acc[i][j] = fmaf(ar[i], br[j], acc[i][j]);
            }
            __syncthreads();
        }
        const float* bI = dir ? bihb : bihf;
        const float* bH = dir ? bhhb : bhhf;
#pragma unroll
        for (int j = 0; j < 4; j++) {
            int col = ncol0 + tx * 4 + j;
            float bias = bI[col] + bH[col];
#pragma unroll
            for (int i = 0; i < 4; i++)
                g_pre[dir][(m0 + ty * 4 + i) * 1024 + col] = acc[i][j] + bias;
        }
    } else {
        __shared__ float ce_s[4][17][16];
        __shared__ int cl_s[4][16];
        const int s0 = (bid - 4096) * 4;
        if (tid < 64) {
            int tk = tid >> 4, w = tid & 15;
            cl_s[tk][w] = char_list[(s0 + tk) * 16 + w];
        }
        __syncthreads();
        for (int idx = tid; idx < 1088; idx += 256) {
            int tk = idx / 272, r = idx % 272;
            int c = r >> 4, w = r & 15;
            ce_s[tk][c][w] = __ldg(&emb[cl_s[tk][w] * 17 + c]);
        }
        __syncthreads();
        const int tl = tid >> 6, o = tid & 63;
        const int s = s0 + tl;
        float r1 = conv_max<2>(ce_s[tl], cw1 + o * 34, cb1[o]);
        float r2 = conv_max<2>(ce_s[tl], cw2 + o * 34, cb2[o]);
        float r3 = conv_max<3>(ce_s[tl], cw3 + o * 51, cb3[o]);
        float r4 = conv_max<3>(ce_s[tl], cw4 + o * 51, cb4[o]);
        g_l[s * 256 + 0 + o] = r1;
        g_l[s * 256 + 64 + o] = r2;
        g_l[s * 256 + 128 + o] = r3;
        g_l[s * 256 + 192 + o] = r4;
    }
}

// =======================================================================
// mbarrier helpers
// =======================================================================
__device__ __forceinline__ void mbar_arm(uint32_t mbar, uint32_t tx) {
    asm volatile("mbarrier.arrive.expect_tx.shared.b64 _, [%0], %1;"
                 :: "r"(mbar), "r"(tx) : "memory");
}
__device__ __forceinline__ void mbar_wait(uint32_t mbar, uint32_t phase) {
    uint32_t done;
    asm volatile(
        "{\n\t.reg .pred p;\n\t"
        "mbarrier.try_wait.parity.acquire.cta.shared::cta.b64 p, [%1], %2;\n\t"
        "selp.b32 %0, 1, 0, p;\n\t}"
        : "=r"(done) : "r"(mbar), "r"(phase) : "memory");
    if (!done) {
        asm volatile(
            "{\n\t.reg .pred P1;\n\t"
            "W1_%=:\n\t"
            "mbarrier.try_wait.parity.acquire.cta.shared::cta.b64 P1, [%0], %1, 0x989680;\n\t"
            "@P1 bra.uni W2_%=;\n\t"
            "bra.uni W1_%=;\n\t"
            "W2_%=:\n\t}"
            :: "r"(mbar), "r"(phase) : "memory");
    }
}

// =======================================================================
// Kernel 2: BiLSTM. grid=16, two 8-CTA clusters (fwd/bwd).
// W_hh register-resident; h exchanged via st.async + mbarrier tx ring.
// =======================================================================
__global__ void __cluster_dims__(8, 1, 1) __launch_bounds__(256, 1)
k_lstm(const float* __restrict__ Whh_f, const float* __restrict__ Whh_b)
{
    __shared__ __align__(16) float hbuf[2][264]; // h[0..127]@[0..127], h[128..255]@[132..259]
    __shared__ float gates_s[128];
    __shared__ __align__(8) unsigned long long mbars[2];

    const int tid = threadIdx.x;
    const int rank = blockIdx.x & 7;
    const int dir = blockIdx.x >> 3;
    const float* __restrict__ Whh = dir ? Whh_b : Whh_f;
    const float* __restrict__ pre = g_pre[dir];
    float* __restrict__ hout = dir ? g_hb : g_hf;

    const int lane = tid & 31;
    const int wrp = tid >> 5;
    const int row_local = wrp * 16 + (lane & 15);   // 0..127 = gate*32 + hu_local
    const int half = lane >> 4;
    const int hoff = half * 132;
    const int gate = row_local >> 5;
    const int hu_local = row_local & 31;
    const int grow = gate * 256 + rank * 32 + hu_local;

    // W_hh slice into registers
    float4 w4[32];
    const float4* wp = reinterpret_cast<const float4*>(Whh + grow * 256 + half * 128);
#pragma unroll
    for (int q = 0; q < 32; q++) w4[q] = __ldg(&wp[q]);

    for (int i = tid; i < 264; i += 256) { hbuf[0][i] = 0.f; hbuf[1][i] = 0.f; }

    uint32_t mb_local = (uint32_t)__cvta_generic_to_shared(&mbars[0]);
    if (tid == 0) {
        asm volatile("mbarrier.init.shared.b64 [%0], 1;" :: "r"(mb_local) : "memory");
        asm volatile("mbarrier.init.shared.b64 [%0], 1;" :: "r"(mb_local + 8) : "memory");
        mbar_arm(mb_local, 1024);      // armed for step-2 data
        mbar_arm(mb_local + 8, 1024);  // armed for step-1 data
    }

    // writer lanes: precompute remote addresses (hoisted mapa)
    uint32_t dA[8], dM[8];
    if (tid < 32) {
        int hu = rank * 32 + tid;
        int hidx = (hu < 128) ? hu : hu + 4;
        uint32_t la = (uint32_t)__cvta_generic_to_shared(&hbuf[0][hidx]);
#pragma unroll
        for (int pr = 0; pr < 8; pr++) {
            asm volatile("mapa.shared::cluster.u32 %0, %1, %2;" : "=r"(dA[pr]) : "r"(la), "r"(pr));
            asm volatile("mapa.shared::cluster.u32 %0, %1, %2;" : "=r"(dM[pr]) : "r"(mb_local), "r"(pr));
        }
    }
    float c = 0.f;
    __syncthreads();
    asm volatile("barrier.cluster.arrive.aligned;" ::: "memory");
    asm volatile("barrier.cluster.wait.aligned;" ::: "memory");

    // 2-deep pre prefetch
    int ti0 = dir ? (SS - 1) : 0;
    int ti1 = dir ? (SS - 2) : 1;
    float pv0 = (half == 0) ? __ldg(&pre[ti0 * 1024 + grow]) : 0.f;
    float pv1 = (half == 0) ? __ldg(&pre[ti1 * 1024 + grow]) : 0.f;

    uint32_t ph0 = 0, ph1 = 0;
    for (int t = 0; t < SS; t++) {
        const int p = t & 1;
        if (t > 0) {
            uint32_t mb = mb_local + (uint32_t)(p << 3);
            if (p) { mbar_wait(mb, ph1); ph1 ^= 1u; }
            else   { mbar_wait(mb, ph0); ph0 ^= 1u; }
            if (tid == 0) mbar_arm(mb, 1024);   // re-arm for t+2
        }
        // prefetch pre for t+2
        int t2 = (t + 2 < SS) ? (t + 2) : (SS - 1);
        int ti2 = dir ? (SS - 1 - t2) : t2;
        float pv2 = (half == 0) ? __ldg(&pre[ti2 * 1024 + grow]) : 0.f;

        // matvec: my half of h dot my weight row
        const float4* h4 = reinterpret_cast<const float4*>(&hbuf[p][hoff]);
        float a0 = 0.f, a1 = 0.f, a2 = 0.f, a3 = 0.f;
#pragma unroll
        for (int q = 0; q < 32; q += 4) {
            float4 h0 = h4[q], hA = h4[q + 1], hB = h4[q + 2], hC = h4[q + 3];
            float4 v0 = w4[q], vA = w4[q + 1], vB = w4[q + 2], vC = w4[q + 3];
            a0 = fmaf(v0.x, h0.x, fmaf(v0.y, h0.y, fmaf(v0.z, h0.z, fmaf(v0.w, h0.w, a0))));
            a1 = fmaf(vA.x, hA.x, fmaf(vA.y, hA.y, fmaf(vA.z, hA.z, fmaf(vA.w, hA.w, a1))));
            a2 = fmaf(vB.x, hB.x, fmaf(vB.y, hB.y, fmaf(vB.z, hB.z, fmaf(vB.w, hB.w, a2))));
            a3 = fmaf(vC.x, hC.x, fmaf(vC.y, hC.y, fmaf(vC.z, hC.z, fmaf(vC.w, hC.w, a3))));
        }
        float acc = (a0 + a1) + (a2 + a3);
        acc += __shfl_xor_sync(0xffffffffu, acc, 16);
        if (half == 0) gates_s[row_local] = acc + pv0;
        __syncthreads();

        if (tid < 32) {
            float gi = gates_s[tid];
            float gf = gates_s[32 + tid];
            float gg = gates_s[64 + tid];
            float go = gates_s[96 + tid];
            float si = __fdividef(1.f, 1.f + __expf(-gi));
            float sf = __fdividef(1.f, 1.f + __expf(-gf));
            float so = __fdividef(1.f, 1.f + __expf(-go));
            float eg = __expf(2.f * gg);
            float tg = 1.f - __fdividef(2.f, eg + 1.f);
            c = sf * c + si * tg;
            float ec = __expf(2.f * c);
            float th = 1.f - __fdividef(2.f, ec + 1.f);
            float hval = so * th;
            if (t + 1 < SS) {
                uint32_t boff = (uint32_t)((t + 1) & 1) * 1056u;   // hbuf stride in bytes
                uint32_t moff = (uint32_t)((t + 1) & 1) * 8u;
                uint32_t hv = __float_as_uint(hval);
#pragma unroll
                for (int pr = 0; pr < 8; pr++) {
                    asm volatile(
                        "st.async.shared::cluster.mbarrier::complete_tx::bytes.u32 [%0], %1, [%2];"
                        :: "r"(dA[pr] + boff), "r"(hv), "r"(dM[pr] + moff) : "memory");
                }
            }
            int tin = dir ? (SS - 1 - t) : t;
            hout[tin * 256 + rank * 32 + tid] = hval;
        }
        pv0 = pv1; pv1 = pv2;
    }
    asm volatile("barrier.cluster.arrive.aligned;" ::: "memory");
    asm volatile("barrier.cluster.wait.aligned;" ::: "memory");
}

// =======================================================================
// Kernel 3: dense emissions  feats = [hf|hb|x|l] @ dense_W^T + b
// =======================================================================
__global__ __launch_bounds__(384) void k_dense(
    const float* __restrict__ x, const float* __restrict__ dW, const float* __restrict__ db)
{
    const int t = blockIdx.x * 8 + threadIdx.x / 48;
    const int j = threadIdx.x % 48;
    const float* __restrict__ w = dW + j * 1024;
    const float* segs[4] = { g_hf + t * 256, g_hb + t * 256, x + t * 256, g_l + t * 256 };
    float acc[4] = { db[j], 0.f, 0.f, 0.f };
#pragma unroll
    for (int sgi = 0; sgi < 4; sgi++) {
        const float4* sv = reinterpret_cast<const float4*>(segs[sgi]);
        const float4* wv = reinterpret_cast<const float4*>(w + sgi * 256);
#pragma unroll 8
        for (int q = 0; q < 64; q++) {
            float4 a = sv[q];
            float4 b = __ldg(&wv[q]);
            acc[q & 3] = fmaf(a.x, b.x, fmaf(a.y, b.y, fmaf(a.z, b.z, fmaf(a.w, b.w, acc[q & 3]))));
        }
    }
    g_feats[t * 48 + j] = (acc[0] + acc[1]) + (acc[2] + acc[3]);
}

// =======================================================================
// Kernel 4: gold path score
// =======================================================================
__global__ __launch_bounds__(256) void k_gold(const int* __restrict__ tags, const float* __restrict__ trans)
{
    __shared__ float red[256];
    const int tid = threadIdx.x;
    float s = 0.f;
    for (int t = tid; t < SS; t += 256) {
        int tg = tags[t];
        s += g_feats[t * 48 + tg];
        int prev = (t == 0) ? STARTT : tags[t - 1];
        s += trans[tg * 48 + prev];
    }
    if (tid == 0) s += trans[ENDT * 48 + tags[SS - 1]];
    red[tid] = s;
    __syncthreads();
    for (int off = 128; off; off >>= 1) {
        if (tid < off) red[tid] += red[tid + off];
        __syncthreads();
    }
    if (tid == 0) g_gold = red[0];
}

// =======================================================================
// Kernel 5: CRF forward scan, LINEAR domain with ZERO-LAG pow2 rescale.
// u_{t+1} = (E . u_t) * exp(feat_t - e2*ln2), e2 = exponent(max u_t),
// computed from the same registers the matvec loads. etot accumulates in int.
// 64 threads = 2 warps x 24 tags, 1 syncthreads per step.
// =======================================================================
__global__ __launch_bounds__(64) void k_crf(const float* __restrict__ trans, float* __restrict__ out)
{
    __shared__ __align__(16) float ush[2][48];
    __shared__ float fin[48];
    const int tid = threadIdx.x;
    const int wz = tid >> 5, lane = tid & 31;
    const bool act = lane < 24;
    const int j = act ? (wz * 24 + lane) : 0;

    float4 E4[12];
#pragma unroll
    for (int q = 0; q < 12; q++) {
        E4[q].x = __expf(__ldg(&trans[j * 48 + q * 4 + 0]));
        E4[q].y = __expf(__ldg(&trans[j * 48 + q * 4 + 1]));
        E4[q].z = __expf(__ldg(&trans[j * 48 + q * 4 + 2]));
        E4[q].w = __expf(__ldg(&trans[j * 48 + q * 4 + 3]));
    }
    float u = (act && j == STARTT) ? 1.f : 0.f;   // u_0 = exp(alpha_0)
    int etot = 0;
    // 4-deep feats prefetch ring
    float f0 = __ldg(&g_feats[0 * 48 + j]);
    float f1 = __ldg(&g_feats[1 * 48 + j]);
    float f2 = __ldg(&g_feats[2 * 48 + j]);
    float f3 = __ldg(&g_feats[3 * 48 + j]);

    for (int t = 0; t < SS; t++) {
        const int p = t & 1;
        if (act) ush[p][j] = u;
        __syncthreads();
        int t4 = (t + 4 < SS) ? (t + 4) : (SS - 1);
        float fnew = __ldg(&g_feats[t4 * 48 + j]);

        const float4* uv = reinterpret_cast<const float4*>(ush[p]);
        float4 x[12];
#pragma unroll
        for (int q = 0; q < 12; q++) x[q] = uv[q];

        // zero-lag scale: exponent of max(u_t) (identical across all threads)
        float4 mm;
        mm.x = fmaxf(x[0].x, x[1].x); mm.y = fmaxf(x[0].y, x[1].y);
        mm.z = fmaxf(x[0].z, x[1].z); mm.w = fmaxf(x[0].w, x[1].w);
#pragma unroll
        for (int q = 2; q < 12; q++) {
            mm.x = fmaxf(mm.x, x[q].x); mm.y = fmaxf(mm.y, x[q].y);
            mm.z = fmaxf(mm.z, x[q].z); mm.w = fmaxf(mm.w, x[q].w);
        }
        float mx = fmaxf(fmaxf(mm.x, mm.y), fmaxf(mm.z, mm.w));
        int e2 = ((__float_as_int(mx) >> 23) & 0xFF) - 127;
        etot += e2;
        float K = __expf(f0 - (float)e2 * 0.69314718f);

        // matvec acc_j = sum_i E[j][i] * u_i
        float a0 = 0.f, a1 = 0.f, a2 = 0.f, a3 = 0.f;
#pragma unroll
        for (int q = 0; q < 12; q += 4) {
            a0 = fmaf(E4[q].x,   x[q].x,   fmaf(E4[q].y,   x[q].y,   fmaf(E4[q].z,   x[q].z,   fmaf(E4[q].w,   x[q].w,   a0))));
            a1 = fmaf(E4[q+1].x, x[q+1].x, fmaf(E4[q+1].y, x[q+1].y, fmaf(E4[q+1].z, x[q+1].z, fmaf(E4[q+1].w, x[q+1].w, a1))));
            a2 = fmaf(E4[q+2].x, x[q+2].x, fmaf(E4[q+2].y, x[q+2].y, fmaf(E4[q+2].z, x[q+2].z, fmaf(E4[q+2].w, x[q+2].w, a2))));
            a3 = fmaf(E4[q+3].x, x[q+3].x, fmaf(E4[q+3].y, x[q+3].y, fmaf(E4[q+3].z, x[q+3].z, fmaf(E4[q+3].w, x[q+3].w, a3))));
        }
        float accv = (a0 + a1) + (a2 + a3);
        u = accv * K;
        f0 = f1; f1 = f2; f2 = f3; f3 = fnew;
    }
    if (act)
        fin[j] = logf(u) + (float)((double)etot * 0.6931471805599453) + __ldg(&trans[ENDT * 48 + j]);
    __syncthreads();
    if (tid == 0) {
        float m = -3.0e38f;
        for (int i = 0; i < 48; i++) m = fmaxf(m, fin[i]);
        float s = 0.f;
        for (int i = 0; i < 48; i++) s += expf(fin[i] - m);
        out[0] = m + logf(s) - g_gold;
    }
}

// =======================================================================
extern "C" void kernel_launch(void* const* d_in, const int* in_sizes, int n_in,
                              void* d_out, int out_size)
{
    const float* sentence  = (const float*)d_in[0];
    const int*   char_list = (const int*)d_in[1];
    const int*   tags      = (const int*)d_in[2];
    const float* emb       = (const float*)d_in[3];
    const float* trans     = (const float*)d_in[4];
    const float* W_ih_f    = (const float*)d_in[5];
    const float* W_hh_f    = (const float*)d_in[6];
    const float* b_ih_f    = (const float*)d_in[7];
    const float* b_hh_f    = (const float*)d_in[8];
    const float* W_ih_b    = (const float*)d_in[9];
    const float* W_hh_b    = (const float*)d_in[10];
    const float* b_ih_b    = (const float*)d_in[11];
    const float* b_hh_b    = (const float*)d_in[12];
    const float* dense_W   = (const float*)d_in[13];
    const float* dense_b   = (const float*)d_in[14];
    const float* cw1 = (const float*)d_in[15];
    const float* cb1 = (const float*)d_in[16];
    const float* cw2 = (const float*)d_in[17];
    const float* cb2 = (const float*)d_in[18];
    const float* cw3 = (const float*)d_in[19];
    const float* cb3 = (const float*)d_in[20];
    const float* cw4 = (const float*)d_in[21];
    const float* cb4 = (const float*)d_in[22];
    float* out = (float*)d_out;

    k_gemm_cnn<<<6144, 256>>>(sentence, W_ih_f, W_ih_b,
                              b_ih_f, b_hh_f, b_ih_b, b_hh_b,
                              char_list, emb,
                              cw1, cb1, cw2, cb2, cw3, cb3, cw4, cb4);
    k_lstm<<<16, 256>>>(W_hh_f, W_hh_b);
    k_dense<<<1024, 384>>>(sentence, dense_W, dense_b);
    k_gold<<<1, 256>>>(tags, trans);
    k_crf<<<1, 64>>>(trans, out);
}